// round 3
// baseline (speedup 1.0000x reference)
#include <cuda_runtime.h>

#define BATCH 1024
#define TT    512
#define DIN   32
#define H     64
#define NB0   4     // batches per block, layer 0
#define NB1   8     // batches per block, layer 1

// Inter-layer h1 stream: [b][t][j] = 1024*512*64 floats (134 MB) static scratch.
__device__ float g_h1[BATCH * TT * H];

__device__ __forceinline__ float sigm(float x) {
    return __fdividef(1.0f, 1.0f + __expf(-x));
}
__device__ __forceinline__ float tanh_f(float x) {
    // tanh(x) = 1 - 2/(e^{2x}+1); exact +-1 limits via __expf/__fdividef
    return 1.0f - __fdividef(2.0f, __expf(2.0f * x) + 1.0f);
}

// ---------------------------------------------------------------------------
// Layer 0: 256 threads = (j in 0..63) x (g in 0..3), NB0 batches per block.
// W_hh row (64f) in registers, W_ih row (32f) in per-thread smem.
// ---------------------------------------------------------------------------
__global__ void __launch_bounds__(256, 2)
lstm_layer0(const float* __restrict__ x,
            const float* __restrict__ Wih, const float* __restrict__ Whh,
            const float* __restrict__ bih, const float* __restrict__ bhh)
{
    __shared__ float4 ws[DIN / 4][256];                 // 32 KB: x-part weights
    __shared__ __align__(16) float xs[2][NB0][DIN];     // staged x_t
    __shared__ __align__(16) float hs[2][NB0][H];       // h ping-pong

    const int tid = threadIdx.x;
    const int j = tid >> 2;
    const int g = tid & 3;
    const int r = g * H + j;               // gate row, PyTorch i,f,g,o order
    const int b0 = blockIdx.x * NB0;

    // one-time weight / bias loads
    #pragma unroll
    for (int kk = 0; kk < DIN / 4; kk++)
        ws[kk][tid] = reinterpret_cast<const float4*>(Wih + r * DIN)[kk];

    float4 wh[H / 4];
    #pragma unroll
    for (int kk = 0; kk < H / 4; kk++)
        wh[kk] = reinterpret_cast<const float4*>(Whh + r * H)[kk];

    const float bias = bih[r] + bhh[r];

    float c[NB0];
    #pragma unroll
    for (int b = 0; b < NB0; b++) c[b] = 0.0f;

    // init h=0, stage x(t=0)
    for (int i = tid; i < NB0 * H; i += 256) ((float*)hs[0])[i] = 0.0f;
    for (int i = tid; i < NB0 * (DIN / 4); i += 256) {
        int b = i / (DIN / 4), kk = i % (DIN / 4);
        ((float4*)xs[0][b])[kk] =
            reinterpret_cast<const float4*>(x + (b0 + b) * TT * DIN)[kk];
    }
    __syncthreads();

    for (int t = 0; t < TT; t++) {
        const int cur = t & 1, nxt = cur ^ 1;

        // prefetch x(t+1) into the other buffer (latency hides under compute)
        if (t + 1 < TT) {
            for (int i = tid; i < NB0 * (DIN / 4); i += 256) {
                int b = i / (DIN / 4), kk = i % (DIN / 4);
                ((float4*)xs[nxt][b])[kk] = reinterpret_cast<const float4*>(
                    x + ((b0 + b) * TT + (t + 1)) * DIN)[kk];
            }
        }

        float acc[NB0];
        #pragma unroll
        for (int b = 0; b < NB0; b++) acc[b] = bias;

        #pragma unroll
        for (int kk = 0; kk < DIN / 4; kk++) {
            float4 w4 = ws[kk][tid];
            #pragma unroll
            for (int b = 0; b < NB0; b++) {
                float4 x4 = ((const float4*)xs[cur][b])[kk];
                acc[b] += w4.x * x4.x + w4.y * x4.y + w4.z * x4.z + w4.w * x4.w;
            }
        }
        #pragma unroll
        for (int kk = 0; kk < H / 4; kk++) {
            #pragma unroll
            for (int b = 0; b < NB0; b++) {
                float4 h4 = ((const float4*)hs[cur][b])[kk];
                acc[b] += wh[kk].x * h4.x + wh[kk].y * h4.y +
                          wh[kk].z * h4.z + wh[kk].w * h4.w;
            }
        }

        const int base = (tid & 31) & ~3;
        #pragma unroll
        for (int b = 0; b < NB0; b++) {
            float ai = __shfl_sync(0xffffffffu, acc[b], base + 0);
            float af = __shfl_sync(0xffffffffu, acc[b], base + 1);
            float ag = __shfl_sync(0xffffffffu, acc[b], base + 2);
            float ao = __shfl_sync(0xffffffffu, acc[b], base + 3);
            if (g == 0) {
                float cc = sigm(af) * c[b] + sigm(ai) * tanh_f(ag);
                c[b] = cc;
                float hh = sigm(ao) * tanh_f(cc);
                hs[nxt][b][j] = hh;
                g_h1[((b0 + b) * TT + t) * H + j] = hh;
            }
        }
        __syncthreads();
    }
}

// ---------------------------------------------------------------------------
// Layer 1 + FC: input D=64 (g_h1). Both weight rows (64+64f) in registers.
// NB1=8 batches/block, 128 blocks, 1 CTA/SM. FC on last h folded into tail.
// ---------------------------------------------------------------------------
__global__ void __launch_bounds__(256, 1)
lstm_layer1(const float* __restrict__ Wih, const float* __restrict__ Whh,
            const float* __restrict__ bih, const float* __restrict__ bhh,
            const float* __restrict__ Wfc, const float* __restrict__ bfc,
            float* __restrict__ out)
{
    __shared__ __align__(16) float xs[2][NB1][H];   // staged h1(t)
    __shared__ __align__(16) float hs[2][NB1][H];   // h ping-pong

    const int tid = threadIdx.x;
    const int j = tid >> 2;
    const int g = tid & 3;
    const int r = g * H + j;
    const int b0 = blockIdx.x * NB1;

    float4 wi[H / 4], wh[H / 4];
    #pragma unroll
    for (int kk = 0; kk < H / 4; kk++) {
        wi[kk] = reinterpret_cast<const float4*>(Wih + r * H)[kk];
        wh[kk] = reinterpret_cast<const float4*>(Whh + r * H)[kk];
    }
    const float bias = bih[r] + bhh[r];

    float c[NB1];
    #pragma unroll
    for (int b = 0; b < NB1; b++) c[b] = 0.0f;

    for (int i = tid; i < NB1 * H; i += 256) ((float*)hs[0])[i] = 0.0f;
    for (int i = tid; i < NB1 * (H / 4); i += 256) {
        int b = i / (H / 4), kk = i % (H / 4);
        ((float4*)xs[0][b])[kk] =
            reinterpret_cast<const float4*>(g_h1 + (b0 + b) * TT * H)[kk];
    }
    __syncthreads();

    for (int t = 0; t < TT; t++) {
        const int cur = t & 1, nxt = cur ^ 1;

        if (t + 1 < TT) {
            for (int i = tid; i < NB1 * (H / 4); i += 256) {
                int b = i / (H / 4), kk = i % (H / 4);
                ((float4*)xs[nxt][b])[kk] = reinterpret_cast<const float4*>(
                    g_h1 + ((b0 + b) * TT + (t + 1)) * H)[kk];
            }
        }

        float acc[NB1];
        #pragma unroll
        for (int b = 0; b < NB1; b++) acc[b] = bias;

        #pragma unroll
        for (int kk = 0; kk < H / 4; kk++) {
            #pragma unroll
            for (int b = 0; b < NB1; b++) {
                float4 x4 = ((const float4*)xs[cur][b])[kk];
                acc[b] += wi[kk].x * x4.x + wi[kk].y * x4.y +
                          wi[kk].z * x4.z + wi[kk].w * x4.w;
            }
        }
        #pragma unroll
        for (int kk = 0; kk < H / 4; kk++) {
            #pragma unroll
            for (int b = 0; b < NB1; b++) {
                float4 h4 = ((const float4*)hs[cur][b])[kk];
                acc[b] += wh[kk].x * h4.x + wh[kk].y * h4.y +
                          wh[kk].z * h4.z + wh[kk].w * h4.w;
            }
        }

        const int base = (tid & 31) & ~3;
        #pragma unroll
        for (int b = 0; b < NB1; b++) {
            float ai = __shfl_sync(0xffffffffu, acc[b], base + 0);
            float af = __shfl_sync(0xffffffffu, acc[b], base + 1);
            float ag = __shfl_sync(0xffffffffu, acc[b], base + 2);
            float ao = __shfl_sync(0xffffffffu, acc[b], base + 3);
            if (g == 0) {
                float cc = sigm(af) * c[b] + sigm(ai) * tanh_f(ag);
                c[b] = cc;
                hs[nxt][b][j] = sigm(ao) * tanh_f(cc);
            }
        }
        __syncthreads();
    }

    // FC: final h is in hs[TT & 1] == hs[0]. One thread per batch.
    if (tid < NB1) {
        float a = bfc[0];
        #pragma unroll
        for (int k = 0; k < H; k++) a += hs[0][tid][k] * Wfc[k];
        out[b0 + tid] = a;
    }
}

extern "C" void kernel_launch(void* const* d_in, const int* in_sizes, int n_in,
                              void* d_out, int out_size)
{
    const float* x    = (const float*)d_in[0];
    const float* Wih0 = (const float*)d_in[1];
    const float* Whh0 = (const float*)d_in[2];
    const float* bih0 = (const float*)d_in[3];
    const float* bhh0 = (const float*)d_in[4];
    const float* Wih1 = (const float*)d_in[5];
    const float* Whh1 = (const float*)d_in[6];
    const float* bih1 = (const float*)d_in[7];
    const float* bhh1 = (const float*)d_in[8];
    const float* Wfc  = (const float*)d_in[9];
    const float* bfc  = (const float*)d_in[10];
    float* out = (float*)d_out;

    lstm_layer0<<<BATCH / NB0, 256>>>(x, Wih0, Whh0, bih0, bhh0);
    lstm_layer1<<<BATCH / NB1, 256>>>(Wih1, Whh1, bih1, bhh1, Wfc, bfc, out);
}

// round 4
// speedup vs baseline: 1.4608x; 1.4608x over previous
#include <cuda_runtime.h>

#define BATCH 1024
#define TT    512
#define DIN   32
#define H     64
#define NROWS 256            // 4*H gate rows
#define NB    4              // batches per block in recurrent kernels
#define BT    (BATCH * TT)

// Static scratch (allocation-free rule): precomputed gate inputs + h1 stream.
__device__ float g_xg0[(size_t)BT * NROWS];   // 537 MB
__device__ float g_xg1[(size_t)BT * NROWS];   // 537 MB
__device__ float g_h1 [(size_t)BT * H];       // 134 MB

// ---------------------------------------------------------------------------
// helpers
// ---------------------------------------------------------------------------
__device__ __forceinline__ void ffma2(unsigned long long& acc,
                                      unsigned long long w,
                                      unsigned long long v) {
    asm("fma.rn.f32x2 %0, %1, %2, %0;" : "+l"(acc) : "l"(w), "l"(v));
}
__device__ __forceinline__ float f2lo(unsigned long long a) {
    return __uint_as_float((unsigned)(a & 0xffffffffull));
}
__device__ __forceinline__ float f2hi(unsigned long long a) {
    return __uint_as_float((unsigned)(a >> 32));
}
__device__ __forceinline__ unsigned long long packlo(float x) {
    return (unsigned long long)__float_as_uint(x);   // (x, 0)
}
__device__ __forceinline__ float tanh_f(float x) {
    // tanh(x) = 1 - 2/(e^{2x}+1); exact +-1 limits
    return 1.0f - __fdividef(2.0f, __expf(2.0f * x) + 1.0f);
}

// Gate row for output slot s: r = (s&3)*64 + (s>>2)  (PyTorch i,f,g,o order,
// arranged so the recurrent kernel's lane tid reads slot tid coalesced).
__device__ __forceinline__ int slot_row(int s) { return (s & 3) * H + (s >> 2); }

// ---------------------------------------------------------------------------
// GEMM: xg[row][slot] = input_row . W_ih[r(slot)] + bih[r] + bhh[r]
// 128 threads, each owns 2 slots (tid, tid+128); 128 input rows per CTA.
// K = DIN (layer0) or H (layer1), compile-time.
// ---------------------------------------------------------------------------
template <int K>
__global__ void __launch_bounds__(128)
gemm_xg(const float* __restrict__ X,      // [BT][K]
        const float* __restrict__ Wih,    // [NROWS][K]
        const float* __restrict__ bih,
        const float* __restrict__ bhh,
        float* __restrict__ out)          // [BT][NROWS]
{
    constexpr int KP = K / 2;             // packed float pairs per row
    constexpr int ROWS = 128;
    __shared__ __align__(16) float xs[ROWS * K];

    const int tid = threadIdx.x;
    const int s0 = tid, s1 = tid + 128;
    const int r0 = slot_row(s0), r1 = slot_row(s1);   // r1 == r0 + 32

    unsigned long long w0[KP], w1[KP];
    #pragma unroll
    for (int i = 0; i < KP; i++) {
        w0[i] = reinterpret_cast<const unsigned long long*>(Wih + r0 * K)[i];
        w1[i] = reinterpret_cast<const unsigned long long*>(Wih + r1 * K)[i];
    }
    const float bias0 = bih[r0] + bhh[r0];
    const float bias1 = bih[r1] + bhh[r1];

    const size_t rowBase = (size_t)blockIdx.x * ROWS;

    // stage tile
    const float4* src = reinterpret_cast<const float4*>(X + rowBase * K);
    float4* dst = reinterpret_cast<float4*>(xs);
    #pragma unroll
    for (int i = tid; i < ROWS * K / 4; i += 128) dst[i] = src[i];
    __syncthreads();

    #pragma unroll 2
    for (int row = 0; row < ROWS; row++) {
        const ulonglong2* xr =
            reinterpret_cast<const ulonglong2*>(xs + row * K);
        unsigned long long a0 = 0ull, a1 = 0ull;
        #pragma unroll
        for (int kk = 0; kk < KP / 2; kk++) {
            ulonglong2 xv = xr[kk];
            ffma2(a0, w0[2 * kk],     xv.x);
            ffma2(a0, w0[2 * kk + 1], xv.y);
            ffma2(a1, w1[2 * kk],     xv.x);
            ffma2(a1, w1[2 * kk + 1], xv.y);
        }
        float* o = out + (rowBase + row) * NROWS;
        o[s0] = bias0 + f2lo(a0) + f2hi(a0);
        o[s1] = bias1 + f2lo(a1) + f2hi(a1);
    }
}

// ---------------------------------------------------------------------------
// Recurrent kernel (shared by both layers): gates = xg(t) + h @ W_hh^T.
// 256 threads = (j 0..63, g 0..3); NB batches/block; 2 CTAs/SM.
// Each lane applies its own gate nonlinearity (sigmoid via tanh identity),
// then activated values are shuffled to the g==0 lane for the cell update.
// ---------------------------------------------------------------------------
template <bool FIRST>
__global__ void __launch_bounds__(256, 2)
lstm_rec(const float* __restrict__ xg,    // [BT][NROWS], bias folded in
         const float* __restrict__ Whh,   // [NROWS][H]
         float* __restrict__ h1out,       // FIRST: [BT][H]
         const float* __restrict__ Wfc,
         const float* __restrict__ bfc,
         float* __restrict__ out)         // !FIRST: [BATCH]
{
    __shared__ __align__(16) float hs[2][NB][H];

    const int tid = threadIdx.x;
    const int j = tid >> 2;
    const int g = tid & 3;
    const int r = g * H + j;
    const int b0 = blockIdx.x * NB;
    const bool lead = (g == 0);

    // activation: act = alpha * tanh(beta * a) + gamma
    const bool g2 = (g == 2);
    const float alpha = g2 ? 1.0f : 0.5f;
    const float beta  = g2 ? 1.0f : 0.5f;
    const float gamma = g2 ? 0.0f : 0.5f;

    unsigned long long wh[H / 2];
    #pragma unroll
    for (int i = 0; i < H / 2; i++)
        wh[i] = reinterpret_cast<const unsigned long long*>(Whh + r * H)[i];

    float c[NB];
    #pragma unroll
    for (int b = 0; b < NB; b++) c[b] = 0.0f;

    for (int i = tid; i < NB * H; i += 256) ((float*)hs[0])[i] = 0.0f;

    // prime xg(t=0)
    float xgc[NB];
    #pragma unroll
    for (int b = 0; b < NB; b++)
        xgc[b] = xg[((size_t)(b0 + b) * TT) * NROWS + tid];
    __syncthreads();

    const int base = (tid & 31) & ~3;

    for (int t = 0; t < TT; t++) {
        const int cur = t & 1, nxt = cur ^ 1;

        // prefetch next step's xg (hides DRAM latency under compute)
        float xgn[NB];
        if (t + 1 < TT) {
            #pragma unroll
            for (int b = 0; b < NB; b++)
                xgn[b] = xg[((size_t)(b0 + b) * TT + (t + 1)) * NROWS + tid];
        }

        unsigned long long acc[NB];
        #pragma unroll
        for (int b = 0; b < NB; b++) acc[b] = packlo(xgc[b]);

        #pragma unroll
        for (int kk = 0; kk < H / 4; kk++) {
            #pragma unroll
            for (int b = 0; b < NB; b++) {
                ulonglong2 hv =
                    reinterpret_cast<const ulonglong2*>(hs[cur][b])[kk];
                ffma2(acc[b], wh[2 * kk],     hv.x);
                ffma2(acc[b], wh[2 * kk + 1], hv.y);
            }
        }

        #pragma unroll
        for (int b = 0; b < NB; b++) {
            float a = f2lo(acc[b]) + f2hi(acc[b]);
            float act = fmaf(alpha, tanh_f(beta * a), gamma);
            float ai = __shfl_sync(0xffffffffu, act, base + 0);
            float af = __shfl_sync(0xffffffffu, act, base + 1);
            float ag = __shfl_sync(0xffffffffu, act, base + 2);
            float ao = __shfl_sync(0xffffffffu, act, base + 3);
            if (lead) {
                float cc = fmaf(af, c[b], ai * ag);
                c[b] = cc;
                float hh = ao * tanh_f(cc);
                hs[nxt][b][j] = hh;
                if (FIRST)
                    h1out[((size_t)(b0 + b) * TT + t) * H + j] = hh;
            }
        }
        #pragma unroll
        for (int b = 0; b < NB; b++) xgc[b] = xgn[b];
        __syncthreads();
    }

    if (!FIRST && tid < NB) {
        // final h is in hs[0] (TT even)
        float a = bfc[0];
        #pragma unroll
        for (int k = 0; k < H; k++) a = fmaf(hs[0][tid][k], Wfc[k], a);
        out[b0 + tid] = a;
    }
}

// ---------------------------------------------------------------------------
extern "C" void kernel_launch(void* const* d_in, const int* in_sizes, int n_in,
                              void* d_out, int out_size)
{
    const float* x    = (const float*)d_in[0];
    const float* Wih0 = (const float*)d_in[1];
    const float* Whh0 = (const float*)d_in[2];
    const float* bih0 = (const float*)d_in[3];
    const float* bhh0 = (const float*)d_in[4];
    const float* Wih1 = (const float*)d_in[5];
    const float* Whh1 = (const float*)d_in[6];
    const float* bih1 = (const float*)d_in[7];
    const float* bhh1 = (const float*)d_in[8];
    const float* Wfc  = (const float*)d_in[9];
    const float* bfc  = (const float*)d_in[10];
    float* out = (float*)d_out;

    float *xg0, *xg1, *h1;
    cudaGetSymbolAddress((void**)&xg0, g_xg0);
    cudaGetSymbolAddress((void**)&xg1, g_xg1);
    cudaGetSymbolAddress((void**)&h1,  g_h1);

    gemm_xg<DIN><<<BT / 128, 128>>>(x, Wih0, bih0, bhh0, xg0);
    lstm_rec<true><<<BATCH / NB, 256>>>(xg0, Whh0, h1, nullptr, nullptr, nullptr);
    gemm_xg<H><<<BT / 128, 128>>>(h1, Wih1, bih1, bhh1, xg1);
    lstm_rec<false><<<BATCH / NB, 256>>>(xg1, Whh1, nullptr, Wfc, bfc, out);
}